// round 1
// baseline (speedup 1.0000x reference)
#include <cuda_runtime.h>
#include <cstddef>

// STFT via four-step FFT: 1024 = 32 x 32.
// One warp per frame; each lane does a fully-unrolled 32-point register FFT.
// Window = Hann = 0.5 - 0.5*cos(2*pi*n/1024) == row 0 of forward_basis (not read).
//
// Output: magnitude (32, 513, 1025) fp32.

#define NS        524288
#define BATCHES   32
#define NFRAMES   1025
#define CUTOFF    513
#define HOP       512
#define FPB       16        // frames per block
#define THREADS   256
#define NWARP     8

// shared layout (floats):
//  twc[1024] | tws[1024] | per-warp tiles 8 x (re[32*33] + im[32*33]) | magbuf[513*17]
#define SM_TWC    0
#define SM_TWS    1024
#define SM_TILE   2048
#define TILE_STRIDE (2*32*33)        // 2112 floats per warp
#define SM_MAG    (SM_TILE + NWARP*TILE_STRIDE)   // 18944
#define SM_FLOATS (SM_MAG + CUTOFF*17)            // 18944 + 8721 = 27665
#define SMEM_BYTES (SM_FLOATS * 4)                // 110660

__device__ __forceinline__ constexpr int brev5(int x) {
    return ((x & 1) << 4) | ((x & 2) << 2) | (x & 4) | ((x & 8) >> 2) | ((x & 16) >> 4);
}

// DIF radix-2 32-point FFT, input natural order, output bit-reversed:
// after the call, a[j] = X[brev5(j)].
__device__ __forceinline__ void fft32(float ar[32], float ai[32]) {
    // TC[m] = cos(2*pi*m/32), TS[m] = sin(2*pi*m/32); twiddle W^m = TC - i*TS
    constexpr float TC[16] = {
        1.0f, 0.9807852804f, 0.9238795325f, 0.8314696123f,
        0.7071067812f, 0.5555702330f, 0.3826834324f, 0.1950903220f,
        0.0f, -0.1950903220f, -0.3826834324f, -0.5555702330f,
        -0.7071067812f, -0.8314696123f, -0.9238795325f, -0.9807852804f };
    constexpr float TS[16] = {
        0.0f, 0.1950903220f, 0.3826834324f, 0.5555702330f,
        0.7071067812f, 0.8314696123f, 0.9238795325f, 0.9807852804f,
        1.0f, 0.9807852804f, 0.9238795325f, 0.8314696123f,
        0.7071067812f, 0.5555702330f, 0.3826834324f, 0.1950903220f };
#pragma unroll
    for (int ls = 5; ls >= 1; --ls) {
        const int half = 1 << (ls - 1);
        const int nblk = 1 << (5 - ls);
        const int step = 1 << (5 - ls);
#pragma unroll
        for (int blk = 0; blk < nblk; ++blk) {
#pragma unroll
            for (int j = 0; j < half; ++j) {
                const int i0 = (blk << ls) + j;
                const int i1 = i0 + half;
                float ur = ar[i0] + ar[i1];
                float ui = ai[i0] + ai[i1];
                float vr = ar[i0] - ar[i1];
                float vi = ai[i0] - ai[i1];
                const float c = TC[j * step];
                const float s = TS[j * step];
                ar[i0] = ur; ai[i0] = ui;
                ar[i1] = vr * c + vi * s;     // (vr + i vi) * (c - i s)
                ai[i1] = vi * c - vr * s;
            }
        }
    }
}

__global__ void __launch_bounds__(THREADS, 2)
stft_kernel(const float* __restrict__ x, float* __restrict__ out) {
    extern __shared__ float sm[];
    float* twc = sm + SM_TWC;
    float* tws = sm + SM_TWS;
    float* magbuf = sm + SM_MAG;

    const int tid  = threadIdx.x;
    const int warp = tid >> 5;
    const int lane = tid & 31;
    float* tre = sm + SM_TILE + warp * TILE_STRIDE;
    float* tim = tre + 32 * 33;

    // Build W_1024 twiddle table: W^m = twc[m] + i*tws[m] = cos - i*sin
    for (int m = tid; m < 1024; m += THREADS) {
        float s, c;
        sincospif((float)m * (1.0f / 512.0f), &s, &c);
        twc[m] = c;
        tws[m] = -s;
    }
    __syncthreads();

    const int b  = blockIdx.y;
    const int t0 = blockIdx.x * FPB;
    const float* __restrict__ xb = x + (size_t)b * NS;

#pragma unroll 1
    for (int sub = 0; sub < FPB / NWARP; ++sub) {
        const int f = warp * (FPB / NWARP) + sub;   // frame slot within block
        const int t = t0 + f;
        if (t < NFRAMES) {
            float ar[32], ai[32];
            // ---- phase 1: load strided samples (n = 32*n1 + lane), window, FFT over n1
            const int base = t * HOP - 512 + lane;
#pragma unroll
            for (int n1 = 0; n1 < 32; ++n1) {
                int idx = base + 32 * n1;
                idx = (idx < 0) ? -idx : idx;                     // reflect left
                idx = (idx >= NS) ? (2 * NS - 2 - idx) : idx;     // reflect right
                const float w = 0.5f - 0.5f * twc[32 * n1 + lane]; // Hann window
                ar[n1] = __ldg(xb + idx) * w;
                ai[n1] = 0.0f;
            }
            fft32(ar, ai);   // ar[j] = A[n2=lane, k1=brev5(j)]

            // ---- phase 2: twiddle by W_1024^{n2*k1}, store transposed into tile
            const float wbr = twc[lane];  // W^lane
            const float wbi = tws[lane];
            float wcr = 1.0f, wci = 0.0f; // W^{lane*k1}, incremental
#pragma unroll
            for (int k1 = 0; k1 < 32; ++k1) {
                const int j = brev5(k1);
                tre[k1 * 33 + lane] = ar[j] * wcr - ai[j] * wci;
                tim[k1 * 33 + lane] = ar[j] * wci + ai[j] * wcr;
                const float nr = wcr * wbr - wci * wbi;
                const float ni = wcr * wbi + wci * wbr;
                wcr = nr; wci = ni;
            }
            __syncwarp();

            // ---- phase 3: lane owns k1 = lane; FFT over n2
#pragma unroll
            for (int n2 = 0; n2 < 32; ++n2) {
                ar[n2] = tre[lane * 33 + n2];
                ai[n2] = tim[lane * 33 + n2];
            }
            __syncwarp();    // tile free for next frame
            fft32(ar, ai);   // ar[j] = X[lane + 32*brev5(j)]

            // ---- phase 4: magnitudes for k = lane + 32*k2 <= 512
#pragma unroll
            for (int k2 = 0; k2 <= 16; ++k2) {
                const int j = brev5(k2);
                const int k = lane + 32 * k2;
                if (k <= 512) {
                    const float m = sqrtf(ar[j] * ar[j] + ai[j] * ai[j]);
                    magbuf[k * 17 + f] = m;
                }
            }
        }
    }
    __syncthreads();

    // ---- phase 5: coalesced writeback, 16 consecutive t per k
    const size_t obase = (size_t)b * CUTOFF * NFRAMES;
    for (int i = tid; i < CUTOFF * FPB; i += THREADS) {
        const int k = i >> 4;
        const int f = i & 15;
        const int t = t0 + f;
        if (t < NFRAMES)
            out[obase + (size_t)k * NFRAMES + t] = magbuf[k * 17 + f];
    }
}

extern "C" void kernel_launch(void* const* d_in, const int* in_sizes, int n_in,
                              void* d_out, int out_size) {
    const float* x = (const float*)d_in[0];
    // d_in[1] = forward_basis: mathematically identical to our windowed DFT; unused.
    float* out = (float*)d_out;

    cudaFuncSetAttribute(stft_kernel,
                         cudaFuncAttributeMaxDynamicSharedMemorySize, SMEM_BYTES);

    dim3 grid((NFRAMES + FPB - 1) / FPB, BATCHES);
    stft_kernel<<<grid, THREADS, SMEM_BYTES>>>(x, out);
}

// round 2
// speedup vs baseline: 2.0757x; 2.0757x over previous
#include <cuda_runtime.h>
#include <cstddef>

// STFT via four-step FFT (1024 = 32x32), REAL-PAIR PACKED:
// each warp packs two consecutive frames as z = w*x_t + i*w*x_{t+1},
// runs one 1024-pt complex FFT (32-pt register FFT per lane + SMEM transpose),
// and unpacks both magnitude spectra via conjugate symmetry + warp shuffle.
//
// Output: magnitude (32, 513, 1025) fp32.

#define NS        524288
#define BATCHES   32
#define NFRAMES   1025
#define CUTOFF    513
#define HOP       512
#define FPB       16        // frames per block (8 warps x 2 frames)
#define THREADS   256
#define NWARP     8
#define FULLMASK  0xFFFFFFFFu

// shared layout (floats):
//  twc[1024] | tws[1024] | per-warp tiles 8 x (re[32*33] + im[32*33]) | magbuf[513*17]
#define SM_TWC    0
#define SM_TWS    1024
#define SM_TILE   2048
#define TILE_STRIDE (2*32*33)        // 2112 floats per warp
#define SM_MAG    (SM_TILE + NWARP*TILE_STRIDE)   // 18944
#define SM_FLOATS (SM_MAG + CUTOFF*17)            // 27665
#define SMEM_BYTES (SM_FLOATS * 4)                // 110660

__device__ __forceinline__ constexpr int brev5(int x) {
    return ((x & 1) << 4) | ((x & 2) << 2) | (x & 4) | ((x & 8) >> 2) | ((x & 16) >> 4);
}

__device__ __forceinline__ float sqrt_fast(float x) {
    float r;
    asm("sqrt.approx.f32 %0, %1;" : "=f"(r) : "f"(x));
    return r;
}

// DIF radix-2 32-point FFT, input natural order, output bit-reversed:
// after the call, a[j] = X[brev5(j)].
__device__ __forceinline__ void fft32(float ar[32], float ai[32]) {
    constexpr float TC[16] = {
        1.0f, 0.9807852804f, 0.9238795325f, 0.8314696123f,
        0.7071067812f, 0.5555702330f, 0.3826834324f, 0.1950903220f,
        0.0f, -0.1950903220f, -0.3826834324f, -0.5555702330f,
        -0.7071067812f, -0.8314696123f, -0.9238795325f, -0.9807852804f };
    constexpr float TS[16] = {
        0.0f, 0.1950903220f, 0.3826834324f, 0.5555702330f,
        0.7071067812f, 0.8314696123f, 0.9238795325f, 0.9807852804f,
        1.0f, 0.9807852804f, 0.9238795325f, 0.8314696123f,
        0.7071067812f, 0.5555702330f, 0.3826834324f, 0.1950903220f };
#pragma unroll
    for (int ls = 5; ls >= 1; --ls) {
        const int half = 1 << (ls - 1);
        const int nblk = 1 << (5 - ls);
        const int step = 1 << (5 - ls);
#pragma unroll
        for (int blk = 0; blk < nblk; ++blk) {
#pragma unroll
            for (int j = 0; j < half; ++j) {
                const int i0 = (blk << ls) + j;
                const int i1 = i0 + half;
                float ur = ar[i0] + ar[i1];
                float ui = ai[i0] + ai[i1];
                float vr = ar[i0] - ar[i1];
                float vi = ai[i0] - ai[i1];
                const float c = TC[j * step];
                const float s = TS[j * step];
                ar[i0] = ur; ai[i0] = ui;
                ar[i1] = vr * c + vi * s;     // (vr + i vi) * (c - i s)
                ai[i1] = vi * c - vr * s;
            }
        }
    }
}

__device__ __forceinline__ int reflect_idx(int idx) {
    idx = (idx < 0) ? -idx : idx;
    idx = (idx >= NS) ? (2 * NS - 2 - idx) : idx;
    return idx;
}

__global__ void __launch_bounds__(THREADS, 2)
stft_kernel(const float* __restrict__ x, float* __restrict__ out) {
    extern __shared__ float sm[];
    float* twc = sm + SM_TWC;
    float* tws = sm + SM_TWS;
    float* magbuf = sm + SM_MAG;

    const int tid  = threadIdx.x;
    const int warp = tid >> 5;
    const int lane = tid & 31;
    float* tre = sm + SM_TILE + warp * TILE_STRIDE;
    float* tim = tre + 32 * 33;

    // Build W_1024 twiddle table: W^m = twc[m] + i*tws[m] = cos - i*sin
    for (int m = tid; m < 1024; m += THREADS) {
        float s, c;
        sincospif((float)m * (1.0f / 512.0f), &s, &c);
        twc[m] = c;
        tws[m] = -s;
    }
    __syncthreads();

    const int b  = blockIdx.y;
    const int t0 = blockIdx.x * FPB;
    const float* __restrict__ xb = x + (size_t)b * NS;

    const int f0 = warp * 2;        // frame slot of first frame of the pair
    const int t  = t0 + f0;         // first frame index (second is t+1)

    if (t < NFRAMES) {
        const bool has2 = (t + 1) < NFRAMES;
        float ar[32], ai[32];

        // ---- phase 1: load both frames (re = frame t, im = frame t+1), window
        const int base = t * HOP - 512 + lane;
#pragma unroll
        for (int n1 = 0; n1 < 32; ++n1) {
            const int n = base + 32 * n1;
            const int i0 = reflect_idx(n);
            const int i1 = reflect_idx(n + 512);
            const float w = 0.5f - 0.5f * twc[32 * n1 + lane]; // Hann window
            ar[n1] = __ldg(xb + i0) * w;
            ai[n1] = __ldg(xb + i1) * w;
        }
        fft32(ar, ai);   // ar[j] = A[n2=lane, k1=brev5(j)]

        // ---- phase 2: twiddle by W_1024^{n2*k1}, transposed store.
        // 4 independent twiddle chains (step W^{4*lane}) to break serial latency.
        float c0r = 1.0f,          c0i = 0.0f;
        float c1r = twc[lane],     c1i = tws[lane];
        float c2r = twc[2 * lane], c2i = tws[2 * lane];
        float c3r = twc[3 * lane], c3i = tws[3 * lane];
        const float w4r = twc[4 * lane];
        const float w4i = tws[4 * lane];

#define TWSTORE(K1, CR, CI)                                        \
        {   const int j_ = brev5(K1);                              \
            tre[(K1) * 33 + lane] = ar[j_] * (CR) - ai[j_] * (CI); \
            tim[(K1) * 33 + lane] = ar[j_] * (CI) + ai[j_] * (CR); }
#define CMULSTEP(CR, CI)                                           \
        {   const float nr_ = (CR) * w4r - (CI) * w4i;             \
            const float ni_ = (CR) * w4i + (CI) * w4r;             \
            (CR) = nr_; (CI) = ni_; }

#pragma unroll
        for (int g = 0; g < 8; ++g) {
            TWSTORE(4 * g + 0, c0r, c0i);
            TWSTORE(4 * g + 1, c1r, c1i);
            TWSTORE(4 * g + 2, c2r, c2i);
            TWSTORE(4 * g + 3, c3r, c3i);
            if (g < 7) {
                CMULSTEP(c0r, c0i);
                CMULSTEP(c1r, c1i);
                CMULSTEP(c2r, c2i);
                CMULSTEP(c3r, c3i);
            }
        }
#undef TWSTORE
#undef CMULSTEP
        __syncwarp();

        // ---- phase 3: lane owns k1 = lane; FFT over n2
#pragma unroll
        for (int n2 = 0; n2 < 32; ++n2) {
            ar[n2] = tre[lane * 33 + n2];
            ai[n2] = tim[lane * 33 + n2];
        }
        fft32(ar, ai);   // ar[j] = Z[k1=lane + 32*brev5(j)]

        // ---- phase 4: conjugate-symmetry unpack + magnitudes.
        // k = lane + 32*k2. Partner N-k lives at lane'=(32-lane)&31, reg k2'=31-k2
        // (lane 0 self-patches with k2'=(32-k2)&31).
        const int src = (32 - lane) & 31;
#pragma unroll
        for (int k2 = 0; k2 < 16; ++k2) {
            const float zr = ar[brev5(k2)];
            const float zi = ai[brev5(k2)];
            float pr = ar[brev5(31 - k2)];
            float pi = ai[brev5(31 - k2)];
            float qr = __shfl_sync(FULLMASK, pr, src);
            float qi = __shfl_sync(FULLMASK, pi, src);
            if (lane == 0) {
                qr = ar[brev5((32 - k2) & 31)];
                qi = ai[brev5((32 - k2) & 31)];
            }
            // X_t[k]   = (Z + conj(Z'))/2 ; X_{t+1}[k] = (Z - conj(Z'))/(2i)
            const float e0r = zr + qr, e0i = zi - qi;
            const float e1r = zr - qr, e1i = zi + qi;
            const float m0 = 0.5f * sqrt_fast(e0r * e0r + e0i * e0i);
            const float m1 = 0.5f * sqrt_fast(e1r * e1r + e1i * e1i);
            const int k = lane + 32 * k2;
            magbuf[k * 17 + f0] = m0;
            if (has2) magbuf[k * 17 + f0 + 1] = m1;
        }
        if (lane == 0) {   // k = 512 (k2 = 16): X_t = Re Z[512], X_{t+1} = Im Z[512]
            const float zr = ar[brev5(16)];
            const float zi = ai[brev5(16)];
            magbuf[512 * 17 + f0] = fabsf(zr);
            if (has2) magbuf[512 * 17 + f0 + 1] = fabsf(zi);
        }
    }
    __syncthreads();

    // ---- phase 5: coalesced writeback, 16 consecutive t per k
    const size_t obase = (size_t)b * CUTOFF * NFRAMES;
    for (int i = tid; i < CUTOFF * FPB; i += THREADS) {
        const int k = i >> 4;
        const int f = i & 15;
        const int tt = t0 + f;
        if (tt < NFRAMES)
            out[obase + (size_t)k * NFRAMES + tt] = magbuf[k * 17 + f];
    }
}

extern "C" void kernel_launch(void* const* d_in, const int* in_sizes, int n_in,
                              void* d_out, int out_size) {
    const float* x = (const float*)d_in[0];
    // d_in[1] = forward_basis: identical to our windowed DFT; unused.
    float* out = (float*)d_out;

    cudaFuncSetAttribute(stft_kernel,
                         cudaFuncAttributeMaxDynamicSharedMemorySize, SMEM_BYTES);

    dim3 grid((NFRAMES + FPB - 1) / FPB, BATCHES);
    stft_kernel<<<grid, THREADS, SMEM_BYTES>>>(x, out);
}

// round 4
// speedup vs baseline: 2.0889x; 1.0064x over previous
#include <cuda_runtime.h>
#include <cstddef>

// STFT via four-step FFT (1024 = 32x32), real-pair packed, 2 LANES PER 32-PT FFT.
// A group of 2 warps (64 lanes) handles one pair of frames; each lane holds
// 16 complex values (32 floats) -> low register pressure, no spills.
// 32-pt FFT = shfl_xor(16) radix-2 stage (const W32 twiddles) + register 16-pt FFT.
//
// Output: magnitude (32, 513, 1025) fp32.

#define NS        524288
#define BATCHES   32
#define NFRAMES   1025
#define CUTOFF    513
#define HOP       512
#define FPB       16        // frames per block (8 groups x 2 frames)
#define THREADS   512
#define NGROUP    8
#define FULLMASK  0xFFFFFFFFu

// shared layout (floats):
//  twc[1024] | tws[1024] | per-group tiles 8 x (re[32*33] + im[32*33]) | magbuf[513*17]
#define SM_TWC    0
#define SM_TWS    1024
#define SM_TILE   2048
#define TILE_STRIDE (2*32*33)        // 2112 floats per group
#define SM_MAG    (SM_TILE + NGROUP*TILE_STRIDE)   // 18944
#define SM_FLOATS (SM_MAG + CUTOFF*17)             // 27665
#define SMEM_BYTES (SM_FLOATS * 4)                 // 110660

__device__ __forceinline__ constexpr int brev4(int x) {
    return ((x & 1) << 3) | ((x & 2) << 1) | ((x & 4) >> 1) | ((x & 8) >> 3);
}

__device__ __forceinline__ float sqrt_fast(float x) {
    float r;
    asm("sqrt.approx.f32 %0, %1;" : "=f"(r) : "f"(x));
    return r;
}

// DIF radix-2 16-point FFT, natural input order, bit-reversed output:
// after the call, a[r] = X[brev4(r)].
__device__ __forceinline__ void fft16(float ar[16], float ai[16]) {
    constexpr float TC[8] = { 1.0f, 0.9238795325f, 0.7071067812f, 0.3826834324f,
                              0.0f, -0.3826834324f, -0.7071067812f, -0.9238795325f };
    constexpr float TS[8] = { 0.0f, 0.3826834324f, 0.7071067812f, 0.9238795325f,
                              1.0f, 0.9238795325f, 0.7071067812f, 0.3826834324f };
#pragma unroll
    for (int ls = 4; ls >= 1; --ls) {
        const int half = 1 << (ls - 1);
        const int nblk = 1 << (4 - ls);
        const int step = 1 << (4 - ls);
#pragma unroll
        for (int blk = 0; blk < nblk; ++blk) {
#pragma unroll
            for (int j = 0; j < half; ++j) {
                const int i0 = (blk << ls) + j;
                const int i1 = i0 + half;
                float ur = ar[i0] + ar[i1];
                float ui = ai[i0] + ai[i1];
                float vr = ar[i0] - ar[i1];
                float vi = ai[i0] - ai[i1];
                const float c = TC[j * step];
                const float s = TS[j * step];
                ar[i0] = ur; ai[i0] = ui;
                ar[i1] = vr * c + vi * s;     // (vr + i vi) * (c - i s)
                ai[i1] = vi * c - vr * s;
            }
        }
    }
}

// Cross-lane radix-2 stage of a 32-pt FFT split over lane pairs (lane, lane^16).
// h = 0 half keeps u = a + a'; h = 1 half keeps v = (a' - a) * W32^j.
__device__ __forceinline__ void cross32(float ar[16], float ai[16], int h) {
    // W32^j = C32[j] - i*S32[j]
    constexpr float C32[16] = {
        1.0f, 0.9807852804f, 0.9238795325f, 0.8314696123f,
        0.7071067812f, 0.5555702330f, 0.3826834324f, 0.1950903220f,
        0.0f, -0.1950903220f, -0.3826834324f, -0.5555702330f,
        -0.7071067812f, -0.8314696123f, -0.9238795325f, -0.9807852804f };
    constexpr float S32[16] = {
        0.0f, 0.1950903220f, 0.3826834324f, 0.5555702330f,
        0.7071067812f, 0.8314696123f, 0.9238795325f, 0.9807852804f,
        1.0f, 0.9807852804f, 0.9238795325f, 0.8314696123f,
        0.7071067812f, 0.5555702330f, 0.3826834324f, 0.1950903220f };
    const bool hi = (h != 0);
#pragma unroll
    for (int j = 0; j < 16; ++j) {
        const float orr = __shfl_xor_sync(FULLMASK, ar[j], 16);
        const float oii = __shfl_xor_sync(FULLMASK, ai[j], 16);
        const float dr = hi ? (orr - ar[j]) : (ar[j] + orr);
        const float di = hi ? (oii - ai[j]) : (ai[j] + oii);
        const float c  = hi ? C32[j] : 1.0f;
        const float s  = hi ? S32[j] : 0.0f;
        ar[j] = dr * c + di * s;
        ai[j] = di * c - dr * s;
    }
}

__device__ __forceinline__ int reflect_idx(int idx) {
    idx = (idx < 0) ? -idx : idx;
    idx = (idx >= NS) ? (2 * NS - 2 - idx) : idx;
    return idx;
}

__global__ void __launch_bounds__(THREADS, 2)
stft_kernel(const float* __restrict__ x, float* __restrict__ out) {
    extern __shared__ float sm[];
    float* twc = sm + SM_TWC;
    float* tws = sm + SM_TWS;
    float* magbuf = sm + SM_MAG;

    const int tid  = threadIdx.x;
    const int warp = tid >> 5;
    const int lane = tid & 31;
    const int l4   = lane & 15;
    const int h    = lane >> 4;          // half-bit within the lane pair
    const int grp  = warp >> 1;          // group of 2 warps = one frame pair
    const int wsub = warp & 1;
    float* tre = sm + SM_TILE + grp * TILE_STRIDE;
    float* tim = tre + 32 * 33;

    // W1024^m = twc[m] + i*tws[m] = cos - i*sin ; Hann window = 0.5 - 0.5*twc[n]
    for (int m = tid; m < 1024; m += THREADS) {
        float s, c;
        sincospif((float)m * (1.0f / 512.0f), &s, &c);
        twc[m] = c;
        tws[m] = -s;
    }
    __syncthreads();

    const int b  = blockIdx.y;
    const int t0 = blockIdx.x * FPB;
    const float* __restrict__ xb = x + (size_t)b * NS;

    const int f0 = grp * 2;
    const int t  = t0 + f0;
    const bool active = (t < NFRAMES);
    const bool has2   = (t + 1) < NFRAMES;

    float ar[16], ai[16];

    if (active) {
        // ---- stage A: columns. lane owns n2, half h of n1.
        const int n2 = l4 + 16 * wsub;
        const int base = t * HOP - 512;
#pragma unroll
        for (int j = 0; j < 16; ++j) {
            const int n  = 512 * h + 32 * j + n2;   // sample offset in frame
            const int i0 = reflect_idx(base + n);
            const int i1 = reflect_idx(base + 512 + n);
            const float w = 0.5f - 0.5f * twc[n];   // Hann
            ar[j] = __ldg(xb + i0) * w;             // frame t   (real part)
            ai[j] = __ldg(xb + i1) * w;             // frame t+1 (imag part)
        }
        cross32(ar, ai, h);
        fft16(ar, ai);     // reg r holds A[n2, k1 = 2*brev4(r) + h]

        // ---- twiddle by W1024^{n2*k1} and transposed store, k1 = 2m + h.
        // 4 chains over p (m = 4q + p), step W^{8*n2}.
        float cr[4], ci[4];
#pragma unroll
        for (int p = 0; p < 4; ++p) {
            const int idx = n2 * (2 * p + h);       // <= 217
            cr[p] = twc[idx];
            ci[p] = tws[idx];
        }
        const float sr = twc[8 * n2];
        const float si = tws[8 * n2];
#pragma unroll
        for (int q = 0; q < 4; ++q) {
#pragma unroll
            for (int p = 0; p < 4; ++p) {
                const int m  = 4 * q + p;
                const int r  = brev4(m);
                const int k1 = 2 * m + h;
                tre[k1 * 33 + n2] = ar[r] * cr[p] - ai[r] * ci[p];
                tim[k1 * 33 + n2] = ar[r] * ci[p] + ai[r] * cr[p];
                if (q < 3) {
                    const float nr = cr[p] * sr - ci[p] * si;
                    const float ni = cr[p] * si + ci[p] * sr;
                    cr[p] = nr; ci[p] = ni;
                }
            }
        }
    }
    __syncthreads();

    if (active) {
        // ---- stage B: rows. k1 -> lane map keeps k1 and 32-k1 in the SAME warp.
        // warp0: l4=0 -> 0, l4=1 -> 16, else pairs (p, 32-p), p = l4>>1 in 1..7
        // warp1: pairs (p, 32-p), p = 8 + (l4>>1) in 8..15
        int k1;
        if (wsub == 0) {
            if (l4 == 0)      k1 = 0;
            else if (l4 == 1) k1 = 16;
            else {
                const int p = l4 >> 1;
                k1 = (l4 & 1) ? (32 - p) : p;
            }
        } else {
            const int p = 8 + (l4 >> 1);
            k1 = (l4 & 1) ? (32 - p) : p;
        }

#pragma unroll
        for (int j = 0; j < 16; ++j) {
            const int n2v = 16 * h + j;
            ar[j] = tre[k1 * 33 + n2v];
            ai[j] = tim[k1 * 33 + n2v];
        }
        cross32(ar, ai, h);
        fft16(ar, ai);     // reg r holds Z[k1 + 32*(2*brev4(r) + h)]

        // ---- conjugate-symmetry unpack + magnitudes.
        // valid outputs (k <= 512) sit at even r; partner value at reg 15-r of:
        //   generic        : lane ^ 17   (k1' = 32-k1 at l4^1, other h)
        //   k1 == 16       : lane ^ 16   (self-pair in k1, other h)    [warp0, l4==1]
        //   k1 == 0        : same lane   (k2' = (32-k2)&31: same h; h==0 via TBL,
        //                                 h==1 is reg 15-r)            [warp0, l4==0]
        // NOTE: special cases are warp0-only (wsub==0) — warp1's l4 0/1 hold k1=8/24.
        const bool k1zero = (wsub == 0) && (l4 == 0);
        const bool k1mid  = (wsub == 0) && (l4 == 1);
        const int msk = k1zero ? 0 : (k1mid ? 16 : 17);
        constexpr int TBL[8] = { 0, 3, 7, 5, 15, 13, 11, 9 };  // k1==0, h==0 partner regs
#pragma unroll
        for (int ri = 0; ri < 8; ++ri) {
            const int r = 2 * ri;
            float qr = __shfl_xor_sync(FULLMASK, ar[15 - r], msk);
            float qi = __shfl_xor_sync(FULLMASK, ai[15 - r], msk);
            if (k1zero && h == 0) { qr = ar[TBL[ri]]; qi = ai[TBL[ri]]; }
            const float zr = ar[r], zi = ai[r];
            const float e0r = zr + qr, e0i = zi - qi;   // X_t[k]   * 2
            const float e1r = zr - qr, e1i = zi + qi;   // X_{t+1}[k] * 2i
            const float m0 = 0.5f * sqrt_fast(e0r * e0r + e0i * e0i);
            const float m1 = 0.5f * sqrt_fast(e1r * e1r + e1i * e1i);
            const int k2 = 2 * brev4(r) + h;
            const int k  = k1 + 32 * k2;
            magbuf[k * 17 + f0] = m0;
            if (has2) magbuf[k * 17 + f0 + 1] = m1;
        }
        if (k1zero && h == 0) {   // k = 512 lives at reg 1 (k2 = 16)
            magbuf[512 * 17 + f0] = fabsf(ar[1]);
            if (has2) magbuf[512 * 17 + f0 + 1] = fabsf(ai[1]);
        }
    }
    __syncthreads();

    // ---- coalesced writeback: 16 consecutive t per k
    const size_t obase = (size_t)b * CUTOFF * NFRAMES;
    for (int i = tid; i < CUTOFF * FPB; i += THREADS) {
        const int k = i >> 4;
        const int f = i & 15;
        const int tt = t0 + f;
        if (tt < NFRAMES)
            out[obase + (size_t)k * NFRAMES + tt] = magbuf[k * 17 + f];
    }
}

extern "C" void kernel_launch(void* const* d_in, const int* in_sizes, int n_in,
                              void* d_out, int out_size) {
    const float* x = (const float*)d_in[0];
    // d_in[1] = forward_basis: identical to our windowed DFT; unused.
    float* out = (float*)d_out;

    cudaFuncSetAttribute(stft_kernel,
                         cudaFuncAttributeMaxDynamicSharedMemorySize, SMEM_BYTES);

    dim3 grid((NFRAMES + FPB - 1) / FPB, BATCHES);
    stft_kernel<<<grid, THREADS, SMEM_BYTES>>>(x, out);
}

// round 7
// speedup vs baseline: 2.1107x; 1.0104x over previous
#include <cuda_runtime.h>
#include <cstddef>

// STFT via four-step FFT (1024 = 32x32), real-pair packed, 2 lanes per 32-pt FFT.
// Round-5: MIO-instruction diet — float2 tile, no twiddle table (trig recurrence),
// packed magnitude stores, per-group named barriers.
//
// Output: magnitude (32, 513, 1025) fp32.

#define NS        524288
#define BATCHES   32
#define NFRAMES   1025
#define CUTOFF    513
#define HOP       512
#define FPB       16        // frames per block (8 groups x 2 frames)
#define THREADS   512
#define NGROUP    8
#define FULLMASK  0xFFFFFFFFu

// shared layout (float2 units):
//  8 group tiles of 32*33 float2  |  mag2[513*9]  (pair (m_t, m_{t+1}) per k, per group)
#define TILE_F2   (32*33)                       // 1056 float2 per group
#define SM_MAG2   (NGROUP * TILE_F2)            // 8448
#define SM_F2     (SM_MAG2 + CUTOFF * 9)        // 8448 + 4617 = 13065
#define SMEM_BYTES (SM_F2 * 8)                  // 104520 B -> 2 blocks/SM

__device__ __forceinline__ constexpr int brev4(int x) {
    return ((x & 1) << 3) | ((x & 2) << 1) | ((x & 4) >> 1) | ((x & 8) >> 3);
}

__device__ __forceinline__ float sqrt_fast(float x) {
    float r;
    asm("sqrt.approx.f32 %0, %1;" : "=f"(r) : "f"(x));
    return r;
}

__device__ __forceinline__ void cmul(float& dr, float& di,
                                     float ar, float ai, float br, float bi) {
    dr = ar * br - ai * bi;
    di = ar * bi + ai * br;
}

// DIF radix-2 16-point FFT, natural input order, bit-reversed output:
// after the call, a[r] = X[brev4(r)].
__device__ __forceinline__ void fft16(float ar[16], float ai[16]) {
    constexpr float TC[8] = { 1.0f, 0.9238795325f, 0.7071067812f, 0.3826834324f,
                              0.0f, -0.3826834324f, -0.7071067812f, -0.9238795325f };
    constexpr float TS[8] = { 0.0f, 0.3826834324f, 0.7071067812f, 0.9238795325f,
                              1.0f, 0.9238795325f, 0.7071067812f, 0.3826834324f };
#pragma unroll
    for (int ls = 4; ls >= 1; --ls) {
        const int half = 1 << (ls - 1);
        const int nblk = 1 << (4 - ls);
        const int step = 1 << (4 - ls);
#pragma unroll
        for (int blk = 0; blk < nblk; ++blk) {
#pragma unroll
            for (int j = 0; j < half; ++j) {
                const int i0 = (blk << ls) + j;
                const int i1 = i0 + half;
                float ur = ar[i0] + ar[i1];
                float ui = ai[i0] + ai[i1];
                float vr = ar[i0] - ar[i1];
                float vi = ai[i0] - ai[i1];
                const float c = TC[j * step];
                const float s = TS[j * step];
                ar[i0] = ur; ai[i0] = ui;
                ar[i1] = vr * c + vi * s;     // (vr + i vi) * (c - i s)
                ai[i1] = vi * c - vr * s;
            }
        }
    }
}

// Cross-lane radix-2 stage of a 32-pt FFT split over lane pairs (lane, lane^16).
// h = 0 half keeps u = a + a'; h = 1 half keeps v = (a' - a) * W32^j.
__device__ __forceinline__ void cross32(float ar[16], float ai[16], int h) {
    constexpr float C32[16] = {
        1.0f, 0.9807852804f, 0.9238795325f, 0.8314696123f,
        0.7071067812f, 0.5555702330f, 0.3826834324f, 0.1950903220f,
        0.0f, -0.1950903220f, -0.3826834324f, -0.5555702330f,
        -0.7071067812f, -0.8314696123f, -0.9238795325f, -0.9807852804f };
    constexpr float S32[16] = {
        0.0f, 0.1950903220f, 0.3826834324f, 0.5555702330f,
        0.7071067812f, 0.8314696123f, 0.9238795325f, 0.9807852804f,
        1.0f, 0.9807852804f, 0.9238795325f, 0.8314696123f,
        0.7071067812f, 0.5555702330f, 0.3826834324f, 0.1950903220f };
    const bool hi = (h != 0);
#pragma unroll
    for (int j = 0; j < 16; ++j) {
        const float orr = __shfl_xor_sync(FULLMASK, ar[j], 16);
        const float oii = __shfl_xor_sync(FULLMASK, ai[j], 16);
        const float dr = hi ? (orr - ar[j]) : (ar[j] + orr);
        const float di = hi ? (oii - ai[j]) : (ai[j] + oii);
        const float c  = hi ? C32[j] : 1.0f;
        const float s  = hi ? S32[j] : 0.0f;
        ar[j] = dr * c + di * s;
        ai[j] = di * c - dr * s;
    }
}

__device__ __forceinline__ int reflect_idx(int idx) {
    idx = (idx < 0) ? -idx : idx;
    idx = (idx >= NS) ? (2 * NS - 2 - idx) : idx;
    return idx;
}

__global__ void __launch_bounds__(THREADS, 2)
stft_kernel(const float* __restrict__ x, float* __restrict__ out) {
    extern __shared__ float2 sm2[];
    float2* mag2 = sm2 + SM_MAG2;

    const int tid  = threadIdx.x;
    const int warp = tid >> 5;
    const int lane = tid & 31;
    const int l4   = lane & 15;
    const int h    = lane >> 4;          // half-bit within the lane pair
    const int grp  = warp >> 1;          // 2-warp group = one frame pair
    const int wsub = warp & 1;
    float2* tile = sm2 + grp * TILE_F2;

    const int b  = blockIdx.y;
    const int t0 = blockIdx.x * FPB;
    const float* __restrict__ xb = x + (size_t)b * NS;

    const int f0 = grp * 2;
    const int t  = t0 + f0;
    const bool active = (t < NFRAMES);

    float ar[16], ai[16];
    const int n2 = l4 + 16 * wsub;

    // One trig call per lane: c0 = cos(pi*n2/512), s0 = sin(pi*n2/512).
    // Serves both the window recurrence seed and all stage-A twiddle seeds.
    float s0, c0;
    sincospif((float)n2 * (1.0f / 512.0f), &s0, &c0);

    if (active) {
        // ---- stage A: load + window (recurrence), cross stage, register FFT16.
        // window w[n] = 0.5 - 0.5*cos(2*pi*n/1024), n = 512h + 32j + n2
        //             = 0.5 - 0.5*(-1)^h * cos(pi*j/16 + pi*n2/512)
        const int base = t * HOP - 512;
        const float Cs = 0.9807852804f, Ss = 0.1950903220f;  // rot by pi/16
        const float wsgn = h ? 0.5f : -0.5f;
        float wcc = c0, wss = s0;
#pragma unroll
        for (int j = 0; j < 16; ++j) {
            const int n  = 512 * h + 32 * j + n2;
            const int i0 = reflect_idx(base + n);
            const int i1 = reflect_idx(base + 512 + n);
            const float w = 0.5f + wsgn * wcc;
            ar[j] = __ldg(xb + i0) * w;             // frame t   (real part)
            ai[j] = __ldg(xb + i1) * w;             // frame t+1 (imag part)
            const float nc = wcc * Cs - wss * Ss;
            wss = wss * Cs + wcc * Ss;
            wcc = nc;
        }
        cross32(ar, ai, h);
        fft16(ar, ai);     // reg r holds A[n2, k1 = 2*brev4(r) + h]

        // ---- twiddle by W1024^{n2*k1}, k1 = 2m + h, m = 4q + p.
        // Seeds W^{n2*(2p+h)} = (h ? W1 : 1) * {1, W2, W4, W6}[p], step W8,
        // all powers of W1 = (c0, -s0) built by complex squaring (no table).
        float w2r, w2i, w4r, w4i, w6r, w6i, w8r, w8i;
        cmul(w2r, w2i, c0, -s0, c0, -s0);          // W^2n2
        cmul(w4r, w4i, w2r, w2i, w2r, w2i);        // W^4n2
        cmul(w6r, w6i, w2r, w2i, w4r, w4i);        // W^6n2
        cmul(w8r, w8i, w4r, w4i, w4r, w4i);        // W^8n2
        const float br = h ? c0 : 1.0f;
        const float bi = h ? -s0 : 0.0f;
        float cr[4], ci[4];
        cr[0] = br;  ci[0] = bi;
        cmul(cr[1], ci[1], br, bi, w2r, w2i);
        cmul(cr[2], ci[2], br, bi, w4r, w4i);
        cmul(cr[3], ci[3], br, bi, w6r, w6i);

#pragma unroll
        for (int q = 0; q < 4; ++q) {
#pragma unroll
            for (int p = 0; p < 4; ++p) {
                const int m  = 4 * q + p;
                const int r  = brev4(m);
                const int k1 = 2 * m + h;
                float vr, vi;
                cmul(vr, vi, ar[r], ai[r], cr[p], ci[p]);
                tile[k1 * 33 + n2] = make_float2(vr, vi);   // STS.64
                if (q < 3) {
                    float nr, ni;
                    cmul(nr, ni, cr[p], ci[p], w8r, w8i);
                    cr[p] = nr; ci[p] = ni;
                }
            }
        }

        // group barrier: order tile stores before tile loads (2 warps, id grp+1)
        asm volatile("bar.sync %0, %1;" :: "r"(grp + 1), "r"(64) : "memory");

        // ---- stage B: k1 -> lane map keeps k1 and 32-k1 in the SAME warp.
        // warp0: l4=0 -> 0, l4=1 -> 16, else pairs (p, 32-p), p = l4>>1 in 1..7
        // warp1: pairs (p, 32-p), p = 8 + (l4>>1) in 8..15
        int k1;
        if (wsub == 0) {
            if (l4 == 0)      k1 = 0;
            else if (l4 == 1) k1 = 16;
            else {
                const int p = l4 >> 1;
                k1 = (l4 & 1) ? (32 - p) : p;
            }
        } else {
            const int p = 8 + (l4 >> 1);
            k1 = (l4 & 1) ? (32 - p) : p;
        }

#pragma unroll
        for (int j = 0; j < 16; ++j) {
            const float2 v = tile[k1 * 33 + 16 * h + j];    // LDS.64
            ar[j] = v.x;
            ai[j] = v.y;
        }
        cross32(ar, ai, h);
        fft16(ar, ai);     // reg r holds Z[k1 + 32*(2*brev4(r) + h)]

        // ---- conjugate-symmetry unpack + magnitudes.
        // partner of even reg r lives at reg 15-r of:
        //   generic  : lane ^ 17  (k1' = 32-k1 at l4^1, other h)
        //   k1 == 16 : lane ^ 16  (warp0, l4==1)
        //   k1 == 0  : same lane  (warp0, l4==0; h==0 via TBL, h==1 reg 15-r)
        const bool k1zero = (wsub == 0) && (l4 == 0);
        const bool k1mid  = (wsub == 0) && (l4 == 1);
        const int msk = k1zero ? 0 : (k1mid ? 16 : 17);
        constexpr int TBL[8] = { 0, 3, 7, 5, 15, 13, 11, 9 };
#pragma unroll
        for (int ri = 0; ri < 8; ++ri) {
            const int r = 2 * ri;
            float qr = __shfl_xor_sync(FULLMASK, ar[15 - r], msk);
            float qi = __shfl_xor_sync(FULLMASK, ai[15 - r], msk);
            if (k1zero && h == 0) { qr = ar[TBL[ri]]; qi = ai[TBL[ri]]; }
            const float zr = ar[r], zi = ai[r];
            const float e0r = zr + qr, e0i = zi - qi;   // X_t[k]     * 2
            const float e1r = zr - qr, e1i = zi + qi;   // X_{t+1}[k] * 2i
            const float m0 = 0.5f * sqrt_fast(e0r * e0r + e0i * e0i);
            const float m1 = 0.5f * sqrt_fast(e1r * e1r + e1i * e1i);
            const int k2 = 2 * brev4(r) + h;
            const int k  = k1 + 32 * k2;
            mag2[k * 9 + grp] = make_float2(m0, m1);    // STS.64
        }
        if (k1zero && h == 0) {   // k = 512 lives at reg 1 (k2 = 16)
            mag2[512 * 9 + grp] = make_float2(fabsf(ar[1]), fabsf(ai[1]));
        }
    }
    __syncthreads();

    // ---- writeback: thread -> (k, group); LDS.64 then two STG.32
    const size_t obase = (size_t)b * CUTOFF * NFRAMES;
    for (int i = tid; i < CUTOFF * NGROUP; i += THREADS) {   // 513*8 = 4104
        const int k = i >> 3;
        const int g = i & 7;
        const float2 v = mag2[k * 9 + g];
        const int tt = t0 + 2 * g;
        float* orow = out + obase + (size_t)k * NFRAMES;
        if (tt < NFRAMES)     orow[tt] = v.x;
        if (tt + 1 < NFRAMES) orow[tt + 1] = v.y;
    }
}

extern "C" void kernel_launch(void* const* d_in, const int* in_sizes, int n_in,
                              void* d_out, int out_size) {
    const float* x = (const float*)d_in[0];
    // d_in[1] = forward_basis: identical to our windowed DFT; unused.
    float* out = (float*)d_out;

    cudaFuncSetAttribute(stft_kernel,
                         cudaFuncAttributeMaxDynamicSharedMemorySize, SMEM_BYTES);

    dim3 grid((NFRAMES + FPB - 1) / FPB, BATCHES);
    stft_kernel<<<grid, THREADS, SMEM_BYTES>>>(x, out);
}